// round 14
// baseline (speedup 1.0000x reference)
#include <cuda_runtime.h>

#define NFEAT 262144
#define NTGT  8192
#define NLAT  32
#define NB    128
#define NC    512
#define NTH   544
#define FB4   (NFEAT/NB/4)
#define YF4   (NTGT/4)
#define YSL4  (YF4/NB)
#define EPSV  1e-7f

#define OFF_MUY  (NFEAT)
#define OFF_U    (NFEAT + NTGT)
#define OFF_WZ   (OFF_U + NLAT)
#define OFF_CZ   (OFF_WZ + NLAT*NFEAT)
#define OFF_TSS  (OFF_CZ + NLAT*NTGT)
#define OFF_BZ   (OFF_TSS + NLAT)
#define OFF_P    (OFF_BZ + NLAT)

/* mailbox: NLAT slots x NB blocks x 4 float4 (15 floats + sig word @15) */
__device__ float4   g_part[NLAT*NB*4];
__device__ unsigned g_sig[NB];

#define BAR1() asm volatile("bar.sync 1, 544;" ::: "memory")
#define BAR2() asm volatile("bar.sync 2, 544;" ::: "memory")

static __device__ __forceinline__ unsigned ld_acq(const unsigned* p){
  unsigned v;
  asm volatile("ld.acquire.gpu.global.u32 %0, [%1];" : "=r"(v) : "l"(p) : "memory");
  return v;
}
static __device__ __forceinline__ void st_rel(unsigned* p, unsigned v){
  asm volatile("st.release.gpu.global.u32 [%0], %1;" :: "l"(p), "r"(v) : "memory");
}
static __device__ __forceinline__ float4 ldcg4(const float4* p){
  float4 v;
  asm volatile("ld.global.cg.v4.f32 {%0,%1,%2,%3}, [%4];"
               : "=f"(v.x),"=f"(v.y),"=f"(v.z),"=f"(v.w) : "l"(p) : "memory");
  return v;
}
static __device__ __forceinline__ void stcg4(float4* p, float4 v){
  asm volatile("st.global.cg.v4.f32 [%0], {%1,%2,%3,%4};"
               :: "l"(p),"f"(v.x),"f"(v.y),"f"(v.z),"f"(v.w) : "memory");
}
static __device__ __forceinline__ void stcg1(float* p, float v){
  asm volatile("st.global.cg.f32 [%0], %1;" :: "l"(p), "f"(v) : "memory");
}
static __device__ __forceinline__ void npause(){
  asm volatile("nanosleep.u32 40;");
}

static __device__ __forceinline__ float d4(float4 a, float4 b){
  return fmaf(a.x,b.x, fmaf(a.y,b.y, fmaf(a.z,b.z, a.w*b.w)));
}
static __device__ __forceinline__ float4 f4fma(float4 a, float s, float4 b){
  float4 r; r.x=fmaf(a.x,s,b.x); r.y=fmaf(a.y,s,b.y);
  r.z=fmaf(a.z,s,b.z); r.w=fmaf(a.w,s,b.w); return r;
}
static __device__ __forceinline__ void f4add(float4& a, float4 b){
  a.x+=b.x; a.y+=b.y; a.z+=b.z; a.w+=b.w;
}

#define SHFL9(mask,o) do{                            \
    a.x += __shfl_xor_sync(mask,a.x,o);              \
    a.y += __shfl_xor_sync(mask,a.y,o);              \
    a.z += __shfl_xor_sync(mask,a.z,o);              \
    a.w += __shfl_xor_sync(mask,a.w,o);              \
    b.x += __shfl_xor_sync(mask,b.x,o);              \
    b.y += __shfl_xor_sync(mask,b.y,o);              \
    b.z += __shfl_xor_sync(mask,b.z,o);              \
    b.w += __shfl_xor_sync(mask,b.w,o);              \
    c0  += __shfl_xor_sync(mask,c0,o);               \
  }while(0)
#define SHFL14(o) do{                                \
    ga.x += __shfl_xor_sync(0xffffffffu,ga.x,o);     \
    ga.y += __shfl_xor_sync(0xffffffffu,ga.y,o);     \
    ga.z += __shfl_xor_sync(0xffffffffu,ga.z,o);     \
    ga.w += __shfl_xor_sync(0xffffffffu,ga.w,o);     \
    gb.x += __shfl_xor_sync(0xffffffffu,gb.x,o);     \
    gb.y += __shfl_xor_sync(0xffffffffu,gb.y,o);     \
    gb.z += __shfl_xor_sync(0xffffffffu,gb.z,o);     \
    gb.w += __shfl_xor_sync(0xffffffffu,gb.w,o);     \
    gc4.x+= __shfl_xor_sync(0xffffffffu,gc4.x,o);    \
    gc4.y+= __shfl_xor_sync(0xffffffffu,gc4.y,o);    \
    gc4.z+= __shfl_xor_sync(0xffffffffu,gc4.z,o);    \
    gc4.w+= __shfl_xor_sync(0xffffffffu,gc4.w,o);    \
    gdx  += __shfl_xor_sync(0xffffffffu,gdx,o);      \
    gdy  += __shfl_xor_sync(0xffffffffu,gdy,o);      \
  }while(0)

/* write 15-float payload + release sig (word 15) */
static __device__ __forceinline__ void post15(int slot, int bid,
                                              float4 pa, float4 pb, float4 pcv,
                                              float pdx, float pdy, unsigned sig){
  float4* mp = &g_part[(slot*NB + bid)*4];
  stcg4(mp,   pa);
  stcg4(mp+1, pb);
  stcg4(mp+2, pcv);
  stcg1((float*)mp+12, pdx);
  stcg1((float*)mp+13, pdy);
  st_rel((unsigned*)((float*)mp+15), sig);
}

/* monolithic 15-float block-reduce + post (prologue/burn-in).
   feature dots: a(4),b(4),c0 over all threads (comm passes zeros).
   target dots t4,t4e: valid pre-reduced on tid0 only.
   ONE __syncthreads inside; caller barriers before s_wA reuse. */
static __device__ __forceinline__ void bredpost15(int slot, int bid, unsigned sig,
                                                  float4 a, float4 b, float c0,
                                                  float4 t4, float t4e,
                                                  float4* s_wA){
  #pragma unroll
  for (int o=16;o>0;o>>=1) SHFL9(0xffffffffu,o);
  int w = threadIdx.x >> 5;
  if ((threadIdx.x & 31) == 0 && threadIdx.x < NC){
    s_wA[w]=a; s_wA[16+w]=b; s_wA[32+w]=make_float4(c0,0.f,0.f,0.f);
  }
  __syncthreads();
  if (threadIdx.x < 32){
    float4 z = make_float4(0.f,0.f,0.f,0.f);
    int l = threadIdx.x;
    a  = (l<16) ? s_wA[l]      : z;
    b  = (l<16) ? s_wA[16+l]   : z;
    c0 = (l<16) ? s_wA[32+l].x : 0.f;
    #pragma unroll
    for (int o=16;o>0;o>>=1) SHFL9(0xffffffffu,o);
    if (threadIdx.x == 0)
      post15(slot, bid, a, b, make_float4(c0, t4.x, t4.y, t4.z),
             t4.w, t4e, sig);
  }
}

/* reduce 5 target floats over warp0 lanes 0-15 (call from tid<16) */
static __device__ __forceinline__ void tred5(float4& t, float& e){
  #pragma unroll
  for (int o=8;o>0;o>>=1){
    t.x += __shfl_xor_sync(0x0000ffffu,t.x,o);
    t.y += __shfl_xor_sync(0x0000ffffu,t.y,o);
    t.z += __shfl_xor_sync(0x0000ffffu,t.z,o);
    t.w += __shfl_xor_sync(0x0000ffffu,t.w,o);
    e   += __shfl_xor_sync(0x0000ffffu,e,o);
  }
}

__global__ void __launch_bounds__(NTH, 1)
ipls_kernel(const float* __restrict__ x,      const float* __restrict__ y,
            const float* __restrict__ mux,    const float* __restrict__ muy,
            const float* __restrict__ u_in,   const float* __restrict__ Wz_in,
            const float* __restrict__ Cz_in,  const float* __restrict__ tss_in,
            const float* __restrict__ bz_in,  const float* __restrict__ P_in,
            const int* __restrict__ n_in,     float* __restrict__ out)
{
  __shared__ float4 s_wA[48];
  __shared__ float4 s_wB[8];
  __shared__ float4 s_wT[2];

  const int tid = threadIdx.x, bid = blockIdx.x;
  const bool feat = (tid < NC);
  const bool yown = (tid < YSL4);
  const unsigned base = ld_acq(&g_sig[bid]);

  const int n   = n_in[0];
  const float fn1  = (float)(n + 1);
  const float fden = (float)(n + 2);

  const float4* W4 = (const float4*)Wz_in;
  const float4* P4 = (const float4*)P_in;
  const float4* C4 = (const float4*)Cz_in;
  const int fidx = bid*FB4 + tid;

  /* ---- init ---- */
  float4 xr = make_float4(0.f,0.f,0.f,0.f);
  float4 yrs = xr;
  float4 wcur=xr, wnext=xr, wnext2=xr, wnext3=xr, pc=xr, pn1=xr, pn2=xr;
  float4 czs0=xr, czs1=xr, czs2=xr, czs3=xr;
  if (feat){
    float4 xv = ((const float4*)x)[fidx];
    float4 mv = ((const float4*)mux)[fidx];
    float4 mu;
    mu.x = (mv.x*fn1 + xv.x)/fden; mu.y = (mv.y*fn1 + xv.y)/fden;
    mu.z = (mv.z*fn1 + xv.z)/fden; mu.w = (mv.w*fn1 + xv.w)/fden;
    ((float4*)out)[fidx] = mu;
    xr.x = xv.x-mu.x; xr.y = xv.y-mu.y; xr.z = xv.z-mu.z; xr.w = xv.w-mu.w;
    wcur   = ldcg4(W4 + fidx);
    wnext  = ldcg4(W4 + (size_t)(NFEAT/4)   + fidx);
    wnext2 = ldcg4(W4 + (size_t)2*(NFEAT/4) + fidx);
    wnext3 = ldcg4(W4 + (size_t)3*(NFEAT/4) + fidx);
    pc     = ldcg4(P4 + fidx);
    pn1    = ldcg4(P4 + (size_t)(NFEAT/4)   + fidx);
    pn2    = ldcg4(P4 + (size_t)2*(NFEAT/4) + fidx);
  }
  if (yown){
    int gi = bid*YSL4 + tid;
    float4 yv = ((const float4*)y)[gi];
    float4 mv = ((const float4*)muy)[gi];
    float4 mu;
    mu.x = (mv.x*fn1 + yv.x)/fden; mu.y = (mv.y*fn1 + yv.y)/fden;
    mu.z = (mv.z*fn1 + yv.z)/fden; mu.w = (mv.w*fn1 + yv.w)/fden;
    ((float4*)(out + OFF_MUY))[gi] = mu;
    yrs.x = yv.x-mu.x; yrs.y = yv.y-mu.y; yrs.z = yv.z-mu.z; yrs.w = yv.w-mu.w;
    czs0 = ldcg4(C4 + bid*YSL4 + tid);
    czs1 = ldcg4(C4 + YF4   + bid*YSL4 + tid);
    czs2 = ldcg4(C4 + 2*YF4 + bid*YSL4 + tid);
    czs3 = ldcg4(C4 + 3*YF4 + bid*YSL4 + tid);
  }

  /* ---- burn-in path (n_new <= 3) ---- */
  if (n + 1 <= 3){
    for (int c=0;c<NLAT;c++){
      float4 a = make_float4(0.f,0.f,0.f,0.f);
      if (feat){
        float u_c = u_in[c];
        float4 w = (c==0)?wcur:((c==1)?wnext:((c==2)?wnext2:((c==3)?wnext3
                 : ldcg4(W4 + (size_t)c*(NFEAT/4) + fidx))));
        float4 wz = f4fma(xr, u_c, w);
        stcg4(((float4*)(out + OFF_WZ)) + (size_t)c*(NFEAT/4) + fidx, wz);
        a = make_float4(d4(xr,wz), d4(wz,wz), 0.f, 0.f);
      }
      float4 z = make_float4(0.f,0.f,0.f,0.f);
      bredpost15(c, bid, base + 1u + (unsigned)c, a, z, 0.f, z, 0.f, s_wA);
      __syncthreads();
    }
    if (bid == 0){
      for (int c=0;c<NLAT;c++){
        __syncthreads();
        if (tid < NB){
          const float4* mp = &g_part[(c*NB + tid)*4];
          while (ld_acq((const unsigned*)((const float*)mp+15)) < base+1u+(unsigned)c)
            npause();
          float4 a = ldcg4(mp);
          float4 b = make_float4(0.f,0.f,0.f,0.f); float c0 = 0.f;
          #pragma unroll
          for (int o=16;o>0;o>>=1) SHFL9(0xffffffffu,o);
          if ((tid & 31) == 0) s_wB[tid>>5] = a;
        }
        __syncthreads();
        if (tid == 0){
          float4 a = s_wB[0];
          f4add(a, s_wB[1]); f4add(a, s_wB[2]); f4add(a, s_wB[3]);
          float tzb = a.x / (sqrtf(a.y) + EPSV);
          out[OFF_TSS + c] = tss_in[c] + tzb*tzb;
          out[OFF_U   + c] = u_in[c];
          out[OFF_BZ  + c] = bz_in[c];
        }
      }
    }
    if (feat){
      int g = bid*NC + tid;
      ((float4*)(out + OFF_CZ))[g] = ((const float4*)Cz_in)[g];
      #pragma unroll 4
      for (int k=0;k<(NLAT*NFEAT/4)/(NB*NC);k++)
        ((float4*)(out + OFF_P))[k*NB*NC + g] = P4[k*NB*NC + g];
    }
    __syncthreads();
    if (tid == 0) st_rel(&g_sig[bid], base + 1000u);
    return;
  }

  /* ---- prologue posts ---- */
  /* slot0: direct invariants of comp 0.
     layout: ga=(A,B,Q,0), gc=(0,F0,E0,G0) */
  {
    float4 t4 = make_float4(0.f,0.f,0.f,0.f); float t4e = 0.f;
    if (yown){
      t4 = make_float4(d4(czs0,yrs), d4(czs0,czs0), d4(yrs,yrs), 0.f);
      tred5(t4, t4e);
    }
    float4 a = make_float4(0.f,0.f,0.f,0.f), b = a;
    if (feat) a = make_float4(d4(xr,wcur), d4(wcur,wcur), d4(xr,xr), 0.f);
    bredpost15(0, bid, base + 1u, a, b, 0.f, t4, 0.f, s_wA);
    __syncthreads();
  }
  /* slot1: 15-float format for comp 1 (m=1, p=-2; identity levels) */
  {
    float4 t4 = make_float4(0.f,0.f,0.f,0.f); float t4e = 0.f;
    if (yown){
      t4 = make_float4(d4(czs1,yrs), 0.f, 0.f, d4(czs1,czs0));
      t4e = d4(czs1,czs1);
      tred5(t4, t4e);
    }
    float4 a = make_float4(0.f,0.f,0.f,0.f), b = a; float c0 = 0.f;
    if (feat){
      a  = make_float4(d4(xr,wnext), 0.f, 0.f, d4(pc,wnext));
      b  = make_float4(d4(wnext,wnext), d4(xr,pc), 0.f, 0.f);
      c0 = d4(pc,pc);
    }
    bredpost15(1, bid, base + 2u, a, b, c0, t4, t4e, s_wA);
    __syncthreads();
  }
  /* slot2: 15-float format for comp 2 (m=2, p=-1) */
  {
    float4 t4 = make_float4(0.f,0.f,0.f,0.f); float t4e = 0.f;
    if (yown){
      t4 = make_float4(d4(czs2,yrs), 0.f, d4(czs2,czs0), d4(czs2,czs1));
      t4e = d4(czs2,czs2);
      tred5(t4, t4e);
    }
    float4 a = make_float4(0.f,0.f,0.f,0.f), b = a; float c0 = 0.f;
    if (feat){
      a  = make_float4(d4(xr,wnext2), 0.f, d4(pc,wnext2), d4(pn1,wnext2));
      b  = make_float4(d4(wnext2,wnext2), d4(xr,pn1), 0.f, d4(pc,pn1));
      c0 = d4(pn1,pn1);
    }
    bredpost15(2, bid, base + 3u, a, b, c0, t4, t4e, s_wA);
  }

  /* direct gather of slot0 */
  float A, B, Q, E, F, G;
  {
    __syncthreads();
    if (tid < NB){
      const float4* mp = &g_part[(0*NB + tid)*4];
      while (ld_acq((const unsigned*)((const float*)mp+15)) < base + 1u) npause();
      float4 a  = ldcg4(mp);
      float4 b  = ldcg4(mp+2);           /* gc */
      float c0 = 0.f;
      #pragma unroll
      for (int o=16;o>0;o>>=1) SHFL9(0xffffffffu,o);
      if ((tid & 31) == 0){ s_wB[tid>>5] = a; s_wB[4+(tid>>5)] = b; }
    }
    __syncthreads();
    float4 a = s_wB[0], b = s_wB[4];
    #pragma unroll
    for (int i=1;i<4;i++){ f4add(a, s_wB[i]); f4add(b, s_wB[4+i]); }
    A = a.x; B = a.y; Q = a.z; F = b.y; E = b.z; G = b.w;
    __syncthreads();   /* s_wB free before loop */
  }

  /* histories for comps c-1 (h1) and c-2 (h2): identity at start */
  float t_h1=0.f, dd_h1=1.f, ss_h1=1.f, kk_h1=0.f;
  float t_h2=0.f, dd_h2=1.f, ss_h2=1.f, kk_h2=0.f;

  /* ---- main scan: depth-3 slack, comm-warp overlapped ---- */
  for (int c=0;c<NLAT;c++){
    const bool do_post   = (c+3 < NLAT);
    const bool do_gather = (c+1 < NLAT);

    if (feat){
      const size_t frow = (size_t)c*(NFEAT/4) + fidx;

      /* stage-1 dots for slot c+3 (basis xr_c / yr_c) */
      if (do_post){
        if (yown){
          float4 t4 = make_float4(d4(czs3,yrs),  d4(czs3,czs0),
                                  d4(czs3,czs1), d4(czs3,czs2));
          float t4e = d4(czs3,czs3);
          tred5(t4, t4e);
          if (tid == 0){ s_wT[0]=t4; s_wT[1]=make_float4(t4e,0.f,0.f,0.f); }
        }
        float4 a = make_float4(d4(xr,wnext3), d4(pc,wnext3),
                               d4(pn1,wnext3), d4(pn2,wnext3));
        float4 b = make_float4(d4(wnext3,wnext3), d4(xr,pn2),
                               d4(pc,pn2), d4(pn1,pn2));
        float c0 = d4(pn2,pn2);
        #pragma unroll
        for (int o=16;o>0;o>>=1) SHFL9(0xffffffffu,o);
        int w = tid >> 5;
        if ((tid & 31) == 0){
          s_wA[w]=a; s_wA[16+w]=b; s_wA[32+w]=make_float4(c0,0.f,0.f,0.f);
        }
      }
      BAR1();

      /* scalar chain comp c */
      const float u0   = u_in[c];
      const float tss0 = tss_in[c];
      const float bz0  = bz_in[c];

      float tz1  = (A + u0*Q) / (sqrtf(fmaxf(B + 2.f*u0*A + u0*u0*Q, 0.f)) + EPSV);
      float tss1 = tss0 + tz1*tz1;
      float t1   = tz1 / sqrtf(tss1);
      float c21  = fmaxf(E + 2.f*t1*F + t1*t1*G, 0.f);
      float u1   = (F + t1*G) / sqrtf(c21);

      float tz   = (A + u1*Q) / (sqrtf(fmaxf(B + 2.f*u1*A + u1*u1*Q, 0.f)) + EPSV);
      float tss_ = tss0 + tz*tz;
      float t    = tz / sqrtf(tss_);
      float c2   = fmaxf(E + 2.f*t*F + t*t*G, 0.f);
      float rc2  = rsqrtf(c2);
      float u_f  = (F + t*G) * rc2;
      float bz_new = bz0 + u_f*tz;
      float bb   = bz_new / sqrtf(tss_);
      float kk   = bb * t * rc2;
      float ss   = 1.f - kk*t;
      float dd   = 1.f - t*t;

      /* vector work */
      stcg4(((float4*)(out + OFF_WZ)) + frow, f4fma(xr, u1, wcur));
      if (yown){
        float4 czk = f4fma(yrs, t, czs0);
        stcg4(((float4*)(out + OFF_CZ)) + (size_t)c*YF4 + bid*YSL4 + tid, czk);
        yrs = f4fma(czk, -kk, yrs);
      }
      if (bid == 0 && tid == 0){
        out[OFF_U   + c] = u_f;
        out[OFF_TSS + c] = tss_;
        out[OFF_BZ  + c] = bz_new;
      }
      float4 pn = f4fma(xr, t, pc);
      stcg4(((float4*)(out + OFF_P)) + frow, pn);
      xr = f4fma(pn, -t, xr);

      float Gn = ss*ss*G - 2.f*ss*kk*F + kk*kk*E;

      /* shift + prefetch (depth 3 on W/Cz, 2 on P) */
      wcur = wnext; wnext = wnext2; wnext2 = wnext3;
      if (c+4 < NLAT)
        wnext3 = ldcg4(W4 + (size_t)(c+4)*(NFEAT/4) + fidx);
      pc = pn1; pn1 = pn2;
      if (c+3 < NLAT)
        pn2 = ldcg4(P4 + (size_t)(c+3)*(NFEAT/4) + fidx);
      czs0 = czs1; czs1 = czs2; czs2 = czs3;
      if (yown && c+4 < NLAT)
        czs3 = ldcg4(C4 + (size_t)(c+4)*YF4 + bid*YSL4 + tid);
      else
        czs3 = make_float4(0.f,0.f,0.f,0.f);

      BAR2();

      /* consume slot c+1 (posted at iter c-2, basis xr_{c-2}/yr_{c-2}):
         3-level correction with h2 (comp c-2), h1 (comp c-1), current */
      if (do_gather){
        float4 ga = s_wB[0], gb = s_wB[1], gc = s_wB[2], gd = s_wB[3];
        float S1 = fmaf(dd_h2, ga.x, -t_h2*ga.y);
        float S2 = fmaf(dd_h1, S1,   -t_h1*ga.z);
        A = fmaf(dd, S2, -t*ga.w);
        B = gb.x;
        float xrPg = fmaf(dd_h1, fmaf(dd_h2, gb.y, -t_h2*gb.z), -t_h1*gb.w);
        Q = dd*dd*Q - 2.f*t*dd*xrPg + t*t*gc.x;
        float T1 = fmaf(ss_h2, gc.y, -kk_h2*gc.z);
        float T2 = fmaf(ss_h1, T1,   -kk_h1*gc.w);
        F = fmaf(ss, T2, -kk*gd.x);
        E = gd.y;
        G = Gn;
        t_h2=t_h1; dd_h2=dd_h1; ss_h2=ss_h1; kk_h2=kk_h1;
        t_h1=t;    dd_h1=dd;    ss_h1=ss;    kk_h1=kk;
      }
    } else {
      /* ======== comm warp (tids 512-543) ======== */
      BAR1();
      if (do_post){
        float4 a, b; float c0;
        {
          float4 z = make_float4(0.f,0.f,0.f,0.f);
          int l = tid - NC;
          a  = (l<16) ? s_wA[l]      : z;
          b  = (l<16) ? s_wA[16+l]   : z;
          c0 = (l<16) ? s_wA[32+l].x : 0.f;
          #pragma unroll
          for (int o=16;o>0;o>>=1) SHFL9(0xffffffffu,o);
        }
        if (tid == NC){
          float4 t4 = s_wT[0]; float t4e = s_wT[1].x;
          post15(c+3, bid, a, b, make_float4(c0, t4.x, t4.y, t4.z),
                 t4.w, t4e, base + 4u + (unsigned)c);
        }
      }
      if (do_gather){
        const int l = tid - NC;
        const unsigned sigval = base + 2u + (unsigned)c;
        float4 ga = make_float4(0.f,0.f,0.f,0.f);
        float4 gb = ga, gc4 = ga;
        float gdx = 0.f, gdy = 0.f;
        #pragma unroll
        for (int k=0;k<4;k++){
          const float4* mp = &g_part[((c+1)*NB + l*4 + k)*4];
          while (ld_acq((const unsigned*)((const float*)mp+15)) < sigval)
            npause();
          float4 pa = ldcg4(mp);
          float4 pb = ldcg4(mp+1);
          float4 pcc= ldcg4(mp+2);
          float4 pd = ldcg4(mp+3);
          f4add(ga, pa); f4add(gb, pb); f4add(gc4, pcc);
          gdx += pd.x; gdy += pd.y;
        }
        #pragma unroll
        for (int o=16;o>0;o>>=1) SHFL14(o);
        if (tid == NC){
          s_wB[0]=ga; s_wB[1]=gb; s_wB[2]=gc4;
          s_wB[3]=make_float4(gdx,gdy,0.f,0.f);
        }
      }
      BAR2();
    }
  }

  __syncthreads();
  if (tid == 0) st_rel(&g_sig[bid], base + 1000u);
}

extern "C" void kernel_launch(void* const* d_in, const int* in_sizes, int n_in,
                              void* d_out, int out_size)
{
  (void)in_sizes; (void)n_in; (void)out_size;
  ipls_kernel<<<NB, NTH>>>(
      (const float*)d_in[0],  (const float*)d_in[1],
      (const float*)d_in[2],  (const float*)d_in[3],
      (const float*)d_in[4],  (const float*)d_in[5],
      (const float*)d_in[6],  (const float*)d_in[7],
      (const float*)d_in[8],  (const float*)d_in[9],
      (const int*)  d_in[10], (float*)d_out);
}

// round 15
// speedup vs baseline: 1.0021x; 1.0021x over previous
#include <cuda_runtime.h>

#define NFEAT 262144
#define NTGT  8192
#define NLAT  32
#define NB    128
#define NC    512            /* compute threads */
#define NTH   544            /* + 1 comm warp  */
#define FB4   (NFEAT/NB/4)
#define YF4   (NTGT/4)
#define YSL4  (YF4/NB)
#define EPSV  1e-7f

#define OFF_MUY  (NFEAT)
#define OFF_U    (NFEAT + NTGT)
#define OFF_WZ   (OFF_U + NLAT)
#define OFF_CZ   (OFF_WZ + NLAT*NFEAT)
#define OFF_TSS  (OFF_CZ + NLAT*NTGT)
#define OFF_BZ   (OFF_TSS + NLAT)
#define OFF_P    (OFF_BZ + NLAT)

/* mailbox: NLAT slots x NB blocks x 3 float4 (11 dots + sig word) */
__device__ float4   g_part[NLAT*NB*3];
__device__ unsigned g_sig[NB];   /* per-launch epoch base only */

#define BAR1() asm volatile("bar.sync 1, 544;" ::: "memory")
#define BAR2() asm volatile("bar.sync 2, 544;" ::: "memory")

static __device__ __forceinline__ unsigned ld_acq(const unsigned* p){
  unsigned v;
  asm volatile("ld.acquire.gpu.global.u32 %0, [%1];" : "=r"(v) : "l"(p) : "memory");
  return v;
}
static __device__ __forceinline__ void st_rel(unsigned* p, unsigned v){
  asm volatile("st.release.gpu.global.u32 [%0], %1;" :: "l"(p), "r"(v) : "memory");
}
static __device__ __forceinline__ float4 ldcg4(const float4* p){
  float4 v;
  asm volatile("ld.global.cg.v4.f32 {%0,%1,%2,%3}, [%4];"
               : "=f"(v.x),"=f"(v.y),"=f"(v.z),"=f"(v.w) : "l"(p) : "memory");
  return v;
}
static __device__ __forceinline__ void stcg4(float4* p, float4 v){
  asm volatile("st.global.cg.v4.f32 [%0], {%1,%2,%3,%4};"
               :: "l"(p),"f"(v.x),"f"(v.y),"f"(v.z),"f"(v.w) : "memory");
}
static __device__ __forceinline__ void stcg1(float* p, float v){
  asm volatile("st.global.cg.f32 [%0], %1;" :: "l"(p), "f"(v) : "memory");
}
static __device__ __forceinline__ void npause(){
  asm volatile("nanosleep.u32 40;");
}

static __device__ __forceinline__ float d4(float4 a, float4 b){
  return fmaf(a.x,b.x, fmaf(a.y,b.y, fmaf(a.z,b.z, a.w*b.w)));
}
static __device__ __forceinline__ float4 f4fma(float4 a, float s, float4 b){
  float4 r; r.x=fmaf(a.x,s,b.x); r.y=fmaf(a.y,s,b.y);
  r.z=fmaf(a.z,s,b.z); r.w=fmaf(a.w,s,b.w); return r;
}
static __device__ __forceinline__ void f4add(float4& a, float4 b){
  a.x+=b.x; a.y+=b.y; a.z+=b.z; a.w+=b.w;
}

#define SHFL8(mask,o) do{                            \
    a.x += __shfl_xor_sync(mask,a.x,o);              \
    a.y += __shfl_xor_sync(mask,a.y,o);              \
    a.z += __shfl_xor_sync(mask,a.z,o);              \
    a.w += __shfl_xor_sync(mask,a.w,o);              \
    b.x += __shfl_xor_sync(mask,b.x,o);              \
    b.y += __shfl_xor_sync(mask,b.y,o);              \
    b.z += __shfl_xor_sync(mask,b.z,o);              \
    b.w += __shfl_xor_sync(mask,b.w,o);              \
  }while(0)
#define SHFL11S(o) do{                               \
    ga.x += __shfl_xor_sync(0xffffffffu,ga.x,o);     \
    ga.y += __shfl_xor_sync(0xffffffffu,ga.y,o);     \
    ga.z += __shfl_xor_sync(0xffffffffu,ga.z,o);     \
    ga.w += __shfl_xor_sync(0xffffffffu,ga.w,o);     \
    gb.x += __shfl_xor_sync(0xffffffffu,gb.x,o);     \
    gb.y += __shfl_xor_sync(0xffffffffu,gb.y,o);     \
    gb.z += __shfl_xor_sync(0xffffffffu,gb.z,o);     \
    gb.w += __shfl_xor_sync(0xffffffffu,gb.w,o);     \
    gc.x += __shfl_xor_sync(0xffffffffu,gc.x,o);     \
    gc.y += __shfl_xor_sync(0xffffffffu,gc.y,o);     \
    gc.z += __shfl_xor_sync(0xffffffffu,gc.z,o);     \
  }while(0)

/* posted slot: [0..3]=a, [4..7]=b(.w=target0), [8..10]=targets1..3, [11]=sig */
static __device__ __forceinline__ void post_sig(int slot, int bid,
                                                float4 a, float4 b, float4 c,
                                                unsigned sig){
  float* mp = (float*)&g_part[(slot*NB + bid)*3];
  stcg4((float4*)mp,     a);
  stcg4((float4*)mp + 1, b);
  stcg1(mp+8,  c.x); stcg1(mp+9, c.y); stcg1(mp+10, c.z);
  st_rel((unsigned*)(mp+11), sig);
}

/* full bred + post (prologue/burn-in; ONE __syncthreads inside) */
static __device__ __forceinline__ void bred_post(int slot, int bid, unsigned sig,
                                                 float4 a, float4 b, float4 t,
                                                 float4* s_wA){
  #pragma unroll
  for (int o=16;o>0;o>>=1) SHFL8(0xffffffffu,o);
  int w = threadIdx.x >> 5;
  if ((threadIdx.x & 31) == 0 && threadIdx.x < NC){ s_wA[w]=a; s_wA[16+w]=b; }
  __syncthreads();
  if (threadIdx.x < 32){
    float4 z = make_float4(0.f,0.f,0.f,0.f);
    int l = threadIdx.x;
    a = (l<16) ? s_wA[l]    : z;
    b = (l<16) ? s_wA[16+l] : z;
    #pragma unroll
    for (int o=16;o>0;o>>=1) SHFL8(0xffffffffu,o);
    if (threadIdx.x == 0){
      b.w = t.x;
      post_sig(slot, bid, a, b, make_float4(t.y,t.z,t.w,0.f), sig);
    }
  }
}

static __device__ __forceinline__ float4 tred16(float4 t){
  #pragma unroll
  for (int o=8;o>0;o>>=1){
    t.x += __shfl_xor_sync(0x0000ffffu,t.x,o);
    t.y += __shfl_xor_sync(0x0000ffffu,t.y,o);
    t.z += __shfl_xor_sync(0x0000ffffu,t.z,o);
    t.w += __shfl_xor_sync(0x0000ffffu,t.w,o);
  }
  return t;
}

/* standalone gather (prologue/burn-in; TWO __syncthreads inside) */
static __device__ __forceinline__ void gather11(int slot, unsigned sigval,
                                                float4& A, float4& B, float4& C,
                                                float4* s_wB){
  __syncthreads();
  if (threadIdx.x < NB){
    const float* mp = (const float*)&g_part[(slot*NB + threadIdx.x)*3];
    while (ld_acq((const unsigned*)(mp+11)) < sigval) npause();
    float4 ga = ldcg4((const float4*)mp);
    float4 gb = ldcg4((const float4*)mp + 1);
    float4 gc = ldcg4((const float4*)mp + 2);
    #pragma unroll
    for (int o=16;o>0;o>>=1) SHFL11S(o);
    if ((threadIdx.x & 31) == 0){
      int w = threadIdx.x >> 5;
      s_wB[w]=ga; s_wB[4+w]=gb; s_wB[8+w]=gc;
    }
  }
  __syncthreads();
  float4 a = s_wB[0], b = s_wB[4], c = s_wB[8];
  #pragma unroll
  for (int i=1;i<4;i++){
    f4add(a, s_wB[i]); f4add(b, s_wB[4+i]);
    c.x += s_wB[8+i].x; c.y += s_wB[8+i].y; c.z += s_wB[8+i].z;
  }
  A=a; B=b; C=c;
}

__global__ void __launch_bounds__(NTH, 1)
ipls_kernel(const float* __restrict__ x,      const float* __restrict__ y,
            const float* __restrict__ mux,    const float* __restrict__ muy,
            const float* __restrict__ u_in,   const float* __restrict__ Wz_in,
            const float* __restrict__ Cz_in,  const float* __restrict__ tss_in,
            const float* __restrict__ bz_in,  const float* __restrict__ P_in,
            const int* __restrict__ n_in,     float* __restrict__ out)
{
  __shared__ float4 s_wA[32];
  __shared__ float4 s_wB[12];
  __shared__ float4 s_wT[1];

  const int tid = threadIdx.x, bid = blockIdx.x;
  const bool feat = (tid < NC);
  const bool yown = (tid < YSL4);
  const unsigned base = ld_acq(&g_sig[bid]);

  const int n   = n_in[0];
  const float fn1  = (float)(n + 1);
  const float fden = (float)(n + 2);

  const float4* W4 = (const float4*)Wz_in;
  const float4* P4 = (const float4*)P_in;
  const float4* C4 = (const float4*)Cz_in;
  const int fidx = bid*FB4 + tid;

  /* ---- init: feature slice + target slice + prefetch (compute only) ---- */
  float4 xr = make_float4(0.f,0.f,0.f,0.f);
  float4 yrs = xr, wcur = xr, wnext = xr, wnext2 = xr, pc = xr, pn1 = xr;
  float4 czs0 = xr, czs1 = xr, czs2 = xr;
  if (feat){
    float4 xv = ((const float4*)x)[fidx];
    float4 mv = ((const float4*)mux)[fidx];
    float4 mu;
    mu.x = (mv.x*fn1 + xv.x)/fden; mu.y = (mv.y*fn1 + xv.y)/fden;
    mu.z = (mv.z*fn1 + xv.z)/fden; mu.w = (mv.w*fn1 + xv.w)/fden;
    ((float4*)out)[fidx] = mu;
    xr.x = xv.x-mu.x; xr.y = xv.y-mu.y; xr.z = xv.z-mu.z; xr.w = xv.w-mu.w;

    wcur   = ldcg4(W4 + fidx);
    wnext  = ldcg4(W4 + (size_t)(NFEAT/4)   + fidx);
    wnext2 = ldcg4(W4 + (size_t)2*(NFEAT/4) + fidx);
    pc     = ldcg4(P4 + fidx);
    pn1    = ldcg4(P4 + (size_t)(NFEAT/4)   + fidx);
  }
  if (yown){
    int gi = bid*YSL4 + tid;
    float4 yv = ((const float4*)y)[gi];
    float4 mv = ((const float4*)muy)[gi];
    float4 mu;
    mu.x = (mv.x*fn1 + yv.x)/fden; mu.y = (mv.y*fn1 + yv.y)/fden;
    mu.z = (mv.z*fn1 + yv.z)/fden; mu.w = (mv.w*fn1 + yv.w)/fden;
    ((float4*)(out + OFF_MUY))[gi] = mu;
    yrs.x = yv.x-mu.x; yrs.y = yv.y-mu.y; yrs.z = yv.z-mu.z; yrs.w = yv.w-mu.w;
    czs0 = ldcg4(C4 + bid*YSL4 + tid);
    czs1 = ldcg4(C4 + YF4   + bid*YSL4 + tid);
    czs2 = ldcg4(C4 + 2*YF4 + bid*YSL4 + tid);
  }

  /* ---- burn-in path (n_new <= 3) ---- */
  if (n + 1 <= 3){
    for (int c=0;c<NLAT;c++){
      float4 a = make_float4(0.f,0.f,0.f,0.f);
      float4 b = a;
      if (feat){
        float u_c = u_in[c];
        float4 w = (c==0) ? wcur : ((c==1) ? wnext : ((c==2) ? wnext2
                 : ldcg4(W4 + (size_t)c*(NFEAT/4) + fidx)));
        float4 wz = f4fma(xr, u_c, w);
        stcg4(((float4*)(out + OFF_WZ)) + (size_t)c*(NFEAT/4) + fidx, wz);
        a = make_float4(d4(xr,wz), d4(wz,wz), 0.f, 0.f);
      }
      bred_post(c, bid, base + 1u + (unsigned)c, a, b, b, s_wA);
      __syncthreads();
    }

    if (bid == 0){
      for (int c=0;c<NLAT;c++){
        float4 ga, gb, gc;
        gather11(c, base + 1u + (unsigned)c, ga, gb, gc, s_wB);
        if (tid == 0){
          float tzb = ga.x / (sqrtf(ga.y) + EPSV);
          out[OFF_TSS + c] = tss_in[c] + tzb*tzb;
          out[OFF_U   + c] = u_in[c];
          out[OFF_BZ  + c] = bz_in[c];
        }
      }
    }
    if (feat){
      int g = bid*NC + tid;
      ((float4*)(out + OFF_CZ))[g] = ((const float4*)Cz_in)[g];
      #pragma unroll 4
      for (int k=0;k<(NLAT*NFEAT/4)/(NB*NC);k++)
        ((float4*)(out + OFF_P))[k*NB*NC + g] = P4[k*NB*NC + g];
    }
    __syncthreads();
    if (tid == 0) st_rel(&g_sig[bid], base + 1000u);
    return;
  }

  /* prologue post slot0: direct invariants of comp 0 */
  {
    float4 t = make_float4(0.f,0.f,0.f,0.f);
    if (yown)
      t = tred16(make_float4(d4(czs0,yrs), d4(czs0,czs0), d4(yrs,yrs), 0.f));
    float4 a = make_float4(0.f,0.f,0.f,0.f), b = a;
    if (feat) a = make_float4(d4(xr,wcur), d4(wcur,wcur), d4(xr,xr), 0.f);
    bred_post(0, bid, base + 1u, a, b, t, s_wA);
    __syncthreads();
  }
  /* prologue post slot1: raw-dot format for comp 1 (xr0 basis) */
  {
    float4 t = make_float4(0.f,0.f,0.f,0.f);
    if (yown)
      t = tred16(make_float4(d4(czs1,yrs), 0.f, d4(czs1,czs0), d4(czs1,czs1)));
    float4 a = make_float4(0.f,0.f,0.f,0.f), b = a;
    if (feat){
      a = make_float4(d4(xr,wnext), 0.f, d4(pc,wnext), d4(wnext,wnext));
      b = make_float4(d4(xr,pc), 0.f, d4(pc,pc), 0.f);
    }
    bred_post(1, bid, base + 2u, a, b, t, s_wA);
  }

  /* gather comp-0 invariants */
  float A, B, Q, E, F, G;
  {
    float4 ga, gb, gc;
    gather11(0, base + 1u, ga, gb, gc, s_wB);
    A = ga.x; B = ga.y; Q = ga.z; F = gb.w; E = gc.x; G = gc.y;
  }
  float t_p = 0.f, dd_p = 1.f, ss_p = 1.f, kk_p = 0.f;

  /* scalar-state register prefetch (off critical path) */
  float u_r = u_in[0], tss_r = tss_in[0], bz_r = bz_in[0];

  /* ---- main scan: comm-warp overlapped, 2 named barriers per iter ---- */
  for (int c=0;c<NLAT;c++){
    const bool do_post   = (c+2 < NLAT);
    const bool do_gather = (c+1 < NLAT);

    if (feat){
      const size_t frow = (size_t)c*(NFEAT/4) + fidx;

      if (do_post){
        if (yown){
          float4 tp = tred16(make_float4(d4(czs2,yrs),  d4(czs2,czs0),
                                         d4(czs2,czs1), d4(czs2,czs2)));
          if (tid == 0) s_wT[0] = tp;
        }
        float4 a = make_float4(d4(xr,wnext2), d4(pc,wnext2),
                               d4(pn1,wnext2), d4(wnext2,wnext2));
        float4 b = make_float4(d4(xr,pn1), d4(pc,pn1), d4(pn1,pn1), 0.f);
        #pragma unroll
        for (int o=16;o>0;o>>=1) SHFL8(0xffffffffu,o);
        int w = tid >> 5;
        if ((tid & 31) == 0){ s_wA[w]=a; s_wA[16+w]=b; }
      }
      BAR1();

      /* scalar chain comp c — division-free, state from registers */
      const float u0   = u_r;
      const float tss0 = tss_r;
      const float bz0  = bz_r;

      float tz1  = (A + u0*Q) * rsqrtf(fmaxf(B + 2.f*u0*A + u0*u0*Q, 1e-30f));
      float tss1 = tss0 + tz1*tz1;
      float t1   = tz1 * rsqrtf(tss1);
      float c21  = fmaxf(E + 2.f*t1*F + t1*t1*G, 1e-30f);
      float u1   = (F + t1*G) * rsqrtf(c21);

      float tz   = (A + u1*Q) * rsqrtf(fmaxf(B + 2.f*u1*A + u1*u1*Q, 1e-30f));
      float tss_ = tss0 + tz*tz;
      float rts  = rsqrtf(tss_);
      float t    = tz * rts;
      float c2   = fmaxf(E + 2.f*t*F + t*t*G, 1e-30f);
      float rc2  = rsqrtf(c2);
      float u_f  = (F + t*G) * rc2;
      float bz_new = bz0 + u_f*tz;
      float bb   = bz_new * rts;
      float kk   = bb * t * rc2;
      float ss   = 1.f - kk*t;
      float dd   = 1.f - t*t;

      /* vector work */
      stcg4(((float4*)(out + OFF_WZ)) + frow, f4fma(xr, u1, wcur));
      if (yown){
        float4 czk = f4fma(yrs, t, czs0);
        stcg4(((float4*)(out + OFF_CZ)) + (size_t)c*YF4 + bid*YSL4 + tid, czk);
        yrs = f4fma(czk, -kk, yrs);
      }
      if (bid == 0 && tid == 0){
        out[OFF_U   + c] = u_f;
        out[OFF_TSS + c] = tss_;
        out[OFF_BZ  + c] = bz_new;
      }
      float4 pn = f4fma(xr, t, pc);
      stcg4(((float4*)(out + OFF_P)) + frow, pn);
      xr = f4fma(pn, -t, xr);

      float Gn = ss*ss*G - 2.f*ss*kk*F + kk*kk*E;

      /* shift + prefetch (incl. next iteration's scalars) */
      wcur = wnext; wnext = wnext2;
      if (c+3 < NLAT)
        wnext2 = ldcg4(W4 + (size_t)(c+3)*(NFEAT/4) + fidx);
      pc = pn1;
      if (c+2 < NLAT)
        pn1 = ldcg4(P4 + (size_t)(c+2)*(NFEAT/4) + fidx);
      czs0 = czs1; czs1 = czs2;
      if (yown && c+3 < NLAT)
        czs2 = ldcg4(C4 + (size_t)(c+3)*YF4 + bid*YSL4 + tid);
      else
        czs2 = make_float4(0.f,0.f,0.f,0.f);
      if (c+1 < NLAT){
        u_r   = u_in[c+1];
        tss_r = tss_in[c+1];
        bz_r  = bz_in[c+1];
      }

      BAR2();

      if (do_gather){
        float4 ga = s_wB[0], gb = s_wB[1], gc = s_wB[2];
        A = dd*fmaf(dd_p, ga.x, -t_p*ga.y) - t*ga.z;
        B = ga.w;
        float xrP = fmaf(dd_p, gb.x, -t_p*gb.y);
        Q = dd*dd*Q - 2.f*t*dd*xrP + t*t*gb.z;
        F = ss*fmaf(ss_p, gb.w, -kk_p*gc.x) - kk*gc.y;
        E = gc.z;
        G = Gn;
        t_p = t; dd_p = dd; ss_p = ss; kk_p = kk;
      }
    } else {
      /* ======== comm warp (tids 512-543) ======== */
      BAR1();
      if (do_post){
        float4 a, b;
        {
          float4 z = make_float4(0.f,0.f,0.f,0.f);
          int l = tid - NC;
          a = (l<16) ? s_wA[l]    : z;
          b = (l<16) ? s_wA[16+l] : z;
          #pragma unroll
          for (int o=16;o>0;o>>=1) SHFL8(0xffffffffu,o);
        }
        if (tid == NC){
          float4 tp = s_wT[0];
          b.w = tp.x;
          post_sig(c+2, bid, a, b, make_float4(tp.y,tp.z,tp.w,0.f),
                   base + 3u + (unsigned)c);
        }
      }
      if (do_gather){
        const int l = tid - NC;               /* 0..31, 4 slots each */
        const unsigned sigval = base + 2u + (unsigned)c;
        float4 ga = make_float4(0.f,0.f,0.f,0.f);
        float4 gb = ga, gc = ga;
        #pragma unroll
        for (int k=0;k<4;k++){
          const float* mp = (const float*)&g_part[((c+1)*NB + l*4 + k)*3];
          while (ld_acq((const unsigned*)(mp+11)) < sigval) npause();
          float4 pa = ldcg4((const float4*)mp);
          float4 pb = ldcg4((const float4*)mp + 1);
          float4 pcv= ldcg4((const float4*)mp + 2);
          f4add(ga, pa); f4add(gb, pb);
          gc.x += pcv.x; gc.y += pcv.y; gc.z += pcv.z;
        }
        #pragma unroll
        for (int o=16;o>0;o>>=1) SHFL11S(o);
        if (tid == NC){ s_wB[0]=ga; s_wB[1]=gb; s_wB[2]=gc; }
      }
      BAR2();
    }
  }

  __syncthreads();
  if (tid == 0) st_rel(&g_sig[bid], base + 1000u);
}

extern "C" void kernel_launch(void* const* d_in, const int* in_sizes, int n_in,
                              void* d_out, int out_size)
{
  (void)in_sizes; (void)n_in; (void)out_size;
  ipls_kernel<<<NB, NTH>>>(
      (const float*)d_in[0],  (const float*)d_in[1],
      (const float*)d_in[2],  (const float*)d_in[3],
      (const float*)d_in[4],  (const float*)d_in[5],
      (const float*)d_in[6],  (const float*)d_in[7],
      (const float*)d_in[8],  (const float*)d_in[9],
      (const int*)  d_in[10], (float*)d_out);
}

// round 16
// speedup vs baseline: 1.0297x; 1.0276x over previous
#include <cuda_runtime.h>

#define NFEAT 262144
#define NTGT  8192
#define NLAT  32
#define NB    128
#define NC    512            /* compute threads */
#define NTH   544            /* + 1 comm warp  */
#define FB4   (NFEAT/NB/4)
#define YF4   (NTGT/4)
#define YSL4  (YF4/NB)
#define EPSV  1e-7f

#define OFF_MUY  (NFEAT)
#define OFF_U    (NFEAT + NTGT)
#define OFF_WZ   (OFF_U + NLAT)
#define OFF_CZ   (OFF_WZ + NLAT*NFEAT)
#define OFF_TSS  (OFF_CZ + NLAT*NTGT)
#define OFF_BZ   (OFF_TSS + NLAT)
#define OFF_P    (OFF_BZ + NLAT)

/* mailbox: NLAT slots x NB blocks x 3 float4 (11 dots + sig word) */
__device__ float4   g_part[NLAT*NB*3];
__device__ unsigned g_sig[NB];   /* per-launch epoch base only */

#define BAR1() asm volatile("bar.sync 1, 544;" ::: "memory")
#define BAR2() asm volatile("bar.sync 2, 544;" ::: "memory")

static __device__ __forceinline__ unsigned ld_acq(const unsigned* p){
  unsigned v;
  asm volatile("ld.acquire.gpu.global.u32 %0, [%1];" : "=r"(v) : "l"(p) : "memory");
  return v;
}
static __device__ __forceinline__ void st_rel(unsigned* p, unsigned v){
  asm volatile("st.release.gpu.global.u32 [%0], %1;" :: "l"(p), "r"(v) : "memory");
}
static __device__ __forceinline__ float4 ldcg4(const float4* p){
  float4 v;
  asm volatile("ld.global.cg.v4.f32 {%0,%1,%2,%3}, [%4];"
               : "=f"(v.x),"=f"(v.y),"=f"(v.z),"=f"(v.w) : "l"(p) : "memory");
  return v;
}
static __device__ __forceinline__ void stcg4(float4* p, float4 v){
  asm volatile("st.global.cg.v4.f32 [%0], {%1,%2,%3,%4};"
               :: "l"(p),"f"(v.x),"f"(v.y),"f"(v.z),"f"(v.w) : "memory");
}
static __device__ __forceinline__ void stcg1(float* p, float v){
  asm volatile("st.global.cg.f32 [%0], %1;" :: "l"(p), "f"(v) : "memory");
}
static __device__ __forceinline__ void npause(){
  asm volatile("nanosleep.u32 40;");
}

static __device__ __forceinline__ float d4(float4 a, float4 b){
  return fmaf(a.x,b.x, fmaf(a.y,b.y, fmaf(a.z,b.z, a.w*b.w)));
}
static __device__ __forceinline__ float4 f4fma(float4 a, float s, float4 b){
  float4 r; r.x=fmaf(a.x,s,b.x); r.y=fmaf(a.y,s,b.y);
  r.z=fmaf(a.z,s,b.z); r.w=fmaf(a.w,s,b.w); return r;
}
static __device__ __forceinline__ void f4add(float4& a, float4 b){
  a.x+=b.x; a.y+=b.y; a.z+=b.z; a.w+=b.w;
}

#define SHFL8(mask,o) do{                            \
    a.x += __shfl_xor_sync(mask,a.x,o);              \
    a.y += __shfl_xor_sync(mask,a.y,o);              \
    a.z += __shfl_xor_sync(mask,a.z,o);              \
    a.w += __shfl_xor_sync(mask,a.w,o);              \
    b.x += __shfl_xor_sync(mask,b.x,o);              \
    b.y += __shfl_xor_sync(mask,b.y,o);              \
    b.z += __shfl_xor_sync(mask,b.z,o);              \
    b.w += __shfl_xor_sync(mask,b.w,o);              \
  }while(0)
#define SHFL11S(o) do{                               \
    ga.x += __shfl_xor_sync(0xffffffffu,ga.x,o);     \
    ga.y += __shfl_xor_sync(0xffffffffu,ga.y,o);     \
    ga.z += __shfl_xor_sync(0xffffffffu,ga.z,o);     \
    ga.w += __shfl_xor_sync(0xffffffffu,ga.w,o);     \
    gb.x += __shfl_xor_sync(0xffffffffu,gb.x,o);     \
    gb.y += __shfl_xor_sync(0xffffffffu,gb.y,o);     \
    gb.z += __shfl_xor_sync(0xffffffffu,gb.z,o);     \
    gb.w += __shfl_xor_sync(0xffffffffu,gb.w,o);     \
    gc.x += __shfl_xor_sync(0xffffffffu,gc.x,o);     \
    gc.y += __shfl_xor_sync(0xffffffffu,gc.y,o);     \
    gc.z += __shfl_xor_sync(0xffffffffu,gc.z,o);     \
  }while(0)

/* posted slot: [0..3]=a, [4..7]=b(.w=target0), [8..10]=targets1..3, [11]=sig */
static __device__ __forceinline__ void post_sig(int slot, int bid,
                                                float4 a, float4 b, float4 c,
                                                unsigned sig){
  float* mp = (float*)&g_part[(slot*NB + bid)*3];
  stcg4((float4*)mp,     a);
  stcg4((float4*)mp + 1, b);
  stcg1(mp+8,  c.x); stcg1(mp+9, c.y); stcg1(mp+10, c.z);
  st_rel((unsigned*)(mp+11), sig);
}

/* full bred + post (prologue/burn-in; ONE __syncthreads inside) */
static __device__ __forceinline__ void bred_post(int slot, int bid, unsigned sig,
                                                 float4 a, float4 b, float4 t,
                                                 float4* s_wA){
  #pragma unroll
  for (int o=16;o>0;o>>=1) SHFL8(0xffffffffu,o);
  int w = threadIdx.x >> 5;
  if ((threadIdx.x & 31) == 0 && threadIdx.x < NC){ s_wA[w]=a; s_wA[16+w]=b; }
  __syncthreads();
  if (threadIdx.x < 32){
    float4 z = make_float4(0.f,0.f,0.f,0.f);
    int l = threadIdx.x;
    a = (l<16) ? s_wA[l]    : z;
    b = (l<16) ? s_wA[16+l] : z;
    #pragma unroll
    for (int o=16;o>0;o>>=1) SHFL8(0xffffffffu,o);
    if (threadIdx.x == 0){
      b.w = t.x;
      post_sig(slot, bid, a, b, make_float4(t.y,t.z,t.w,0.f), sig);
    }
  }
}

static __device__ __forceinline__ float4 tred16(float4 t){
  #pragma unroll
  for (int o=8;o>0;o>>=1){
    t.x += __shfl_xor_sync(0x0000ffffu,t.x,o);
    t.y += __shfl_xor_sync(0x0000ffffu,t.y,o);
    t.z += __shfl_xor_sync(0x0000ffffu,t.z,o);
    t.w += __shfl_xor_sync(0x0000ffffu,t.w,o);
  }
  return t;
}

/* standalone gather (prologue/burn-in; TWO __syncthreads inside) */
static __device__ __forceinline__ void gather11(int slot, unsigned sigval,
                                                float4& A, float4& B, float4& C,
                                                float4* s_wB){
  __syncthreads();
  if (threadIdx.x < NB){
    const float* mp = (const float*)&g_part[(slot*NB + threadIdx.x)*3];
    while (ld_acq((const unsigned*)(mp+11)) < sigval) npause();
    float4 ga = ldcg4((const float4*)mp);
    float4 gb = ldcg4((const float4*)mp + 1);
    float4 gc = ldcg4((const float4*)mp + 2);
    #pragma unroll
    for (int o=16;o>0;o>>=1) SHFL11S(o);
    if ((threadIdx.x & 31) == 0){
      int w = threadIdx.x >> 5;
      s_wB[w]=ga; s_wB[4+w]=gb; s_wB[8+w]=gc;
    }
  }
  __syncthreads();
  float4 a = s_wB[0], b = s_wB[4], c = s_wB[8];
  #pragma unroll
  for (int i=1;i<4;i++){
    f4add(a, s_wB[i]); f4add(b, s_wB[4+i]);
    c.x += s_wB[8+i].x; c.y += s_wB[8+i].y; c.z += s_wB[8+i].z;
  }
  A=a; B=b; C=c;
}

__global__ void __launch_bounds__(NTH, 1)
ipls_kernel(const float* __restrict__ x,      const float* __restrict__ y,
            const float* __restrict__ mux,    const float* __restrict__ muy,
            const float* __restrict__ u_in,   const float* __restrict__ Wz_in,
            const float* __restrict__ Cz_in,  const float* __restrict__ tss_in,
            const float* __restrict__ bz_in,  const float* __restrict__ P_in,
            const int* __restrict__ n_in,     float* __restrict__ out)
{
  __shared__ float4 s_wA[32];
  __shared__ float4 s_wB[12];
  __shared__ float4 s_wT[1];

  const int tid = threadIdx.x, bid = blockIdx.x;
  const bool feat = (tid < NC);
  const bool yown = (tid < YSL4);
  const unsigned base = ld_acq(&g_sig[bid]);

  const int n   = n_in[0];
  const float fn1  = (float)(n + 1);
  const float fden = (float)(n + 2);

  const float4* W4 = (const float4*)Wz_in;
  const float4* P4 = (const float4*)P_in;
  const float4* C4 = (const float4*)Cz_in;
  const int fidx = bid*FB4 + tid;

  /* ---- init: feature slice + target slice + prefetch (compute only) ---- */
  float4 xr = make_float4(0.f,0.f,0.f,0.f);
  float4 yrs = xr, wcur = xr, wnext = xr, wnext2 = xr, pc = xr, pn1 = xr;
  float4 czs0 = xr, czs1 = xr, czs2 = xr;
  if (feat){
    float4 xv = ((const float4*)x)[fidx];
    float4 mv = ((const float4*)mux)[fidx];
    float4 mu;
    mu.x = (mv.x*fn1 + xv.x)/fden; mu.y = (mv.y*fn1 + xv.y)/fden;
    mu.z = (mv.z*fn1 + xv.z)/fden; mu.w = (mv.w*fn1 + xv.w)/fden;
    ((float4*)out)[fidx] = mu;
    xr.x = xv.x-mu.x; xr.y = xv.y-mu.y; xr.z = xv.z-mu.z; xr.w = xv.w-mu.w;

    wcur   = ldcg4(W4 + fidx);
    wnext  = ldcg4(W4 + (size_t)(NFEAT/4)   + fidx);
    wnext2 = ldcg4(W4 + (size_t)2*(NFEAT/4) + fidx);
    pc     = ldcg4(P4 + fidx);
    pn1    = ldcg4(P4 + (size_t)(NFEAT/4)   + fidx);
  }
  if (yown){
    int gi = bid*YSL4 + tid;
    float4 yv = ((const float4*)y)[gi];
    float4 mv = ((const float4*)muy)[gi];
    float4 mu;
    mu.x = (mv.x*fn1 + yv.x)/fden; mu.y = (mv.y*fn1 + yv.y)/fden;
    mu.z = (mv.z*fn1 + yv.z)/fden; mu.w = (mv.w*fn1 + yv.w)/fden;
    ((float4*)(out + OFF_MUY))[gi] = mu;
    yrs.x = yv.x-mu.x; yrs.y = yv.y-mu.y; yrs.z = yv.z-mu.z; yrs.w = yv.w-mu.w;
    czs0 = ldcg4(C4 + bid*YSL4 + tid);
    czs1 = ldcg4(C4 + YF4   + bid*YSL4 + tid);
    czs2 = ldcg4(C4 + 2*YF4 + bid*YSL4 + tid);
  }

  /* ---- burn-in path (n_new <= 3) ---- */
  if (n + 1 <= 3){
    for (int c=0;c<NLAT;c++){
      float4 a = make_float4(0.f,0.f,0.f,0.f);
      float4 b = a;
      if (feat){
        float u_c = u_in[c];
        float4 w = (c==0) ? wcur : ((c==1) ? wnext : ((c==2) ? wnext2
                 : ldcg4(W4 + (size_t)c*(NFEAT/4) + fidx)));
        float4 wz = f4fma(xr, u_c, w);
        stcg4(((float4*)(out + OFF_WZ)) + (size_t)c*(NFEAT/4) + fidx, wz);
        a = make_float4(d4(xr,wz), d4(wz,wz), 0.f, 0.f);
      }
      bred_post(c, bid, base + 1u + (unsigned)c, a, b, b, s_wA);
      __syncthreads();
    }

    if (bid == 0){
      for (int c=0;c<NLAT;c++){
        float4 ga, gb, gc;
        gather11(c, base + 1u + (unsigned)c, ga, gb, gc, s_wB);
        if (tid == 0){
          float tzb = ga.x / (sqrtf(ga.y) + EPSV);
          out[OFF_TSS + c] = tss_in[c] + tzb*tzb;
          out[OFF_U   + c] = u_in[c];
          out[OFF_BZ  + c] = bz_in[c];
        }
      }
    }
    if (feat){
      int g = bid*NC + tid;
      ((float4*)(out + OFF_CZ))[g] = ((const float4*)Cz_in)[g];
      #pragma unroll 4
      for (int k=0;k<(NLAT*NFEAT/4)/(NB*NC);k++)
        ((float4*)(out + OFF_P))[k*NB*NC + g] = P4[k*NB*NC + g];
    }
    __syncthreads();
    if (tid == 0) st_rel(&g_sig[bid], base + 1000u);
    return;
  }

  /* prologue post slot0: direct invariants of comp 0 */
  {
    float4 t = make_float4(0.f,0.f,0.f,0.f);
    if (yown)
      t = tred16(make_float4(d4(czs0,yrs), d4(czs0,czs0), d4(yrs,yrs), 0.f));
    float4 a = make_float4(0.f,0.f,0.f,0.f), b = a;
    if (feat) a = make_float4(d4(xr,wcur), d4(wcur,wcur), d4(xr,xr), 0.f);
    bred_post(0, bid, base + 1u, a, b, t, s_wA);
    __syncthreads();
  }
  /* prologue post slot1: raw-dot format for comp 1 (xr0 basis) */
  {
    float4 t = make_float4(0.f,0.f,0.f,0.f);
    if (yown)
      t = tred16(make_float4(d4(czs1,yrs), 0.f, d4(czs1,czs0), d4(czs1,czs1)));
    float4 a = make_float4(0.f,0.f,0.f,0.f), b = a;
    if (feat){
      a = make_float4(d4(xr,wnext), 0.f, d4(pc,wnext), d4(wnext,wnext));
      b = make_float4(d4(xr,pc), 0.f, d4(pc,pc), 0.f);
    }
    bred_post(1, bid, base + 2u, a, b, t, s_wA);
  }

  /* gather comp-0 invariants */
  float A, B, Q, E, F, G;
  {
    float4 ga, gb, gc;
    gather11(0, base + 1u, ga, gb, gc, s_wB);
    A = ga.x; B = ga.y; Q = ga.z; F = gb.w; E = gc.x; G = gc.y;
  }
  float t_p = 0.f, dd_p = 1.f, ss_p = 1.f, kk_p = 0.f;

  /* scalar-state register prefetch (off critical path) */
  float u_r = u_in[0], tss_r = tss_in[0], bz_r = bz_in[0];

  /* ---- main scan: comm-warp overlapped, 2 named barriers per iter ---- */
  for (int c=0;c<NLAT;c++){
    const bool do_post   = (c+2 < NLAT);
    const bool do_gather = (c+1 < NLAT);

    if (feat){
      const size_t frow = (size_t)c*(NFEAT/4) + fidx;

      if (do_post){
        if (yown){
          float4 tp = tred16(make_float4(d4(czs2,yrs),  d4(czs2,czs0),
                                         d4(czs2,czs1), d4(czs2,czs2)));
          if (tid == 0) s_wT[0] = tp;
        }
        float4 a = make_float4(d4(xr,wnext2), d4(pc,wnext2),
                               d4(pn1,wnext2), d4(wnext2,wnext2));
        float4 b = make_float4(d4(xr,pn1), d4(pc,pn1), d4(pn1,pn1), 0.f);
        #pragma unroll
        for (int o=16;o>0;o>>=1) SHFL8(0xffffffffu,o);
        int w = tid >> 5;
        if ((tid & 31) == 0){ s_wA[w]=a; s_wA[16+w]=b; }
      }
      BAR1();

      /* scalar chain comp c — division-free, state from registers */
      const float u0   = u_r;
      const float tss0 = tss_r;
      const float bz0  = bz_r;

      float tz1  = (A + u0*Q) * rsqrtf(fmaxf(B + 2.f*u0*A + u0*u0*Q, 1e-30f));
      float tss1 = tss0 + tz1*tz1;
      float t1   = tz1 * rsqrtf(tss1);
      float c21  = fmaxf(E + 2.f*t1*F + t1*t1*G, 1e-30f);
      float u1   = (F + t1*G) * rsqrtf(c21);

      float tz   = (A + u1*Q) * rsqrtf(fmaxf(B + 2.f*u1*A + u1*u1*Q, 1e-30f));
      float tss_ = tss0 + tz*tz;
      float rts  = rsqrtf(tss_);
      float t    = tz * rts;
      float c2   = fmaxf(E + 2.f*t*F + t*t*G, 1e-30f);
      float rc2  = rsqrtf(c2);
      float u_f  = (F + t*G) * rc2;
      float bz_new = bz0 + u_f*tz;
      float bb   = bz_new * rts;
      float kk   = bb * t * rc2;
      float ss   = 1.f - kk*t;
      float dd   = 1.f - t*t;

      /* vector work */
      stcg4(((float4*)(out + OFF_WZ)) + frow, f4fma(xr, u1, wcur));
      if (yown){
        float4 czk = f4fma(yrs, t, czs0);
        stcg4(((float4*)(out + OFF_CZ)) + (size_t)c*YF4 + bid*YSL4 + tid, czk);
        yrs = f4fma(czk, -kk, yrs);
      }
      if (bid == 0 && tid == 0){
        out[OFF_U   + c] = u_f;
        out[OFF_TSS + c] = tss_;
        out[OFF_BZ  + c] = bz_new;
      }
      float4 pn = f4fma(xr, t, pc);
      stcg4(((float4*)(out + OFF_P)) + frow, pn);
      xr = f4fma(pn, -t, xr);

      float Gn = ss*ss*G - 2.f*ss*kk*F + kk*kk*E;

      /* shift + prefetch (incl. next iteration's scalars) */
      wcur = wnext; wnext = wnext2;
      if (c+3 < NLAT)
        wnext2 = ldcg4(W4 + (size_t)(c+3)*(NFEAT/4) + fidx);
      pc = pn1;
      if (c+2 < NLAT)
        pn1 = ldcg4(P4 + (size_t)(c+2)*(NFEAT/4) + fidx);
      czs0 = czs1; czs1 = czs2;
      if (yown && c+3 < NLAT)
        czs2 = ldcg4(C4 + (size_t)(c+3)*YF4 + bid*YSL4 + tid);
      else
        czs2 = make_float4(0.f,0.f,0.f,0.f);
      if (c+1 < NLAT){
        u_r   = u_in[c+1];
        tss_r = tss_in[c+1];
        bz_r  = bz_in[c+1];
      }

      BAR2();

      if (do_gather){
        float4 ga = s_wB[0], gb = s_wB[1], gc = s_wB[2];
        A = dd*fmaf(dd_p, ga.x, -t_p*ga.y) - t*ga.z;
        B = ga.w;
        float xrP = fmaf(dd_p, gb.x, -t_p*gb.y);
        Q = dd*dd*Q - 2.f*t*dd*xrP + t*t*gb.z;
        F = ss*fmaf(ss_p, gb.w, -kk_p*gc.x) - kk*gc.y;
        E = gc.z;
        G = Gn;
        t_p = t; dd_p = dd; ss_p = ss; kk_p = kk;
      }
    } else {
      /* ======== comm warp (tids 512-543) ======== */
      BAR1();
      if (do_post){
        float4 a, b;
        {
          float4 z = make_float4(0.f,0.f,0.f,0.f);
          int l = tid - NC;
          a = (l<16) ? s_wA[l]    : z;
          b = (l<16) ? s_wA[16+l] : z;
          #pragma unroll
          for (int o=16;o>0;o>>=1) SHFL8(0xffffffffu,o);
        }
        if (tid == NC){
          float4 tp = s_wT[0];
          b.w = tp.x;
          post_sig(c+2, bid, a, b, make_float4(tp.y,tp.z,tp.w,0.f),
                   base + 3u + (unsigned)c);
        }
      }
      if (do_gather){
        const int l = tid - NC;               /* 0..31, 4 slots each */
        const unsigned sigval = base + 2u + (unsigned)c;
        float4 ga = make_float4(0.f,0.f,0.f,0.f);
        float4 gb = ga, gc = ga;
        #pragma unroll
        for (int k=0;k<4;k++){
          const float* mp = (const float*)&g_part[((c+1)*NB + l*4 + k)*3];
          /* pure acquire-spin: bounded by one L2 round-trip per miss */
          while (ld_acq((const unsigned*)(mp+11)) < sigval) { }
          float4 pa = ldcg4((const float4*)mp);
          float4 pb = ldcg4((const float4*)mp + 1);
          float4 pcv= ldcg4((const float4*)mp + 2);
          f4add(ga, pa); f4add(gb, pb);
          gc.x += pcv.x; gc.y += pcv.y; gc.z += pcv.z;
        }
        #pragma unroll
        for (int o=16;o>0;o>>=1) SHFL11S(o);
        if (tid == NC){ s_wB[0]=ga; s_wB[1]=gb; s_wB[2]=gc; }
      }
      BAR2();
    }
  }

  __syncthreads();
  if (tid == 0) st_rel(&g_sig[bid], base + 1000u);
}

extern "C" void kernel_launch(void* const* d_in, const int* in_sizes, int n_in,
                              void* d_out, int out_size)
{
  (void)in_sizes; (void)n_in; (void)out_size;
  ipls_kernel<<<NB, NTH>>>(
      (const float*)d_in[0],  (const float*)d_in[1],
      (const float*)d_in[2],  (const float*)d_in[3],
      (const float*)d_in[4],  (const float*)d_in[5],
      (const float*)d_in[6],  (const float*)d_in[7],
      (const float*)d_in[8],  (const float*)d_in[9],
      (const int*)  d_in[10], (float*)d_out);
}

// round 17
// speedup vs baseline: 1.5289x; 1.4848x over previous
#include <cuda_runtime.h>

#define NFEAT 262144
#define NTGT  8192
#define NLAT  32
#define NB    128
#define NC    512            /* compute threads */
#define NTH   544            /* + 1 comm warp  */
#define FB4   (NFEAT/NB/4)
#define YF4   (NTGT/4)
#define YSL4  (YF4/NB)
#define EPSV  1e-7f

#define OFF_MUY  (NFEAT)
#define OFF_U    (NFEAT + NTGT)
#define OFF_WZ   (OFF_U + NLAT)
#define OFF_CZ   (OFF_WZ + NLAT*NFEAT)
#define OFF_TSS  (OFF_CZ + NLAT*NTGT)
#define OFF_BZ   (OFF_TSS + NLAT)
#define OFF_P    (OFF_BZ + NLAT)

/* mailbox: NLAT slots x NB blocks x 3 float4 (11 dots + sig word) */
__device__ float4   g_part[NLAT*NB*3];
__device__ unsigned g_sig[NB];   /* per-launch epoch base only */

#define BAR1() asm volatile("bar.sync 1, 544;" ::: "memory")
#define BAR2() asm volatile("bar.sync 2, 544;" ::: "memory")

static __device__ __forceinline__ unsigned ld_acq(const unsigned* p){
  unsigned v;
  asm volatile("ld.acquire.gpu.global.u32 %0, [%1];" : "=r"(v) : "l"(p) : "memory");
  return v;
}
static __device__ __forceinline__ void st_rel(unsigned* p, unsigned v){
  asm volatile("st.release.gpu.global.u32 [%0], %1;" :: "l"(p), "r"(v) : "memory");
}
static __device__ __forceinline__ float4 ldcg4(const float4* p){
  float4 v;
  asm volatile("ld.global.cg.v4.f32 {%0,%1,%2,%3}, [%4];"
               : "=f"(v.x),"=f"(v.y),"=f"(v.z),"=f"(v.w) : "l"(p) : "memory");
  return v;
}
static __device__ __forceinline__ void stcg4(float4* p, float4 v){
  asm volatile("st.global.cg.v4.f32 [%0], {%1,%2,%3,%4};"
               :: "l"(p),"f"(v.x),"f"(v.y),"f"(v.z),"f"(v.w) : "memory");
}
static __device__ __forceinline__ void stcg1(float* p, float v){
  asm volatile("st.global.cg.f32 [%0], %1;" :: "l"(p), "f"(v) : "memory");
}
static __device__ __forceinline__ void npause(){
  asm volatile("nanosleep.u32 40;");
}

static __device__ __forceinline__ float d4(float4 a, float4 b){
  return fmaf(a.x,b.x, fmaf(a.y,b.y, fmaf(a.z,b.z, a.w*b.w)));
}
static __device__ __forceinline__ float4 f4fma(float4 a, float s, float4 b){
  float4 r; r.x=fmaf(a.x,s,b.x); r.y=fmaf(a.y,s,b.y);
  r.z=fmaf(a.z,s,b.z); r.w=fmaf(a.w,s,b.w); return r;
}
static __device__ __forceinline__ void f4add(float4& a, float4 b){
  a.x+=b.x; a.y+=b.y; a.z+=b.z; a.w+=b.w;
}

#define SHFL8(mask,o) do{                            \
    a.x += __shfl_xor_sync(mask,a.x,o);              \
    a.y += __shfl_xor_sync(mask,a.y,o);              \
    a.z += __shfl_xor_sync(mask,a.z,o);              \
    a.w += __shfl_xor_sync(mask,a.w,o);              \
    b.x += __shfl_xor_sync(mask,b.x,o);              \
    b.y += __shfl_xor_sync(mask,b.y,o);              \
    b.z += __shfl_xor_sync(mask,b.z,o);              \
    b.w += __shfl_xor_sync(mask,b.w,o);              \
  }while(0)
#define SHFL11S(o) do{                               \
    ga.x += __shfl_xor_sync(0xffffffffu,ga.x,o);     \
    ga.y += __shfl_xor_sync(0xffffffffu,ga.y,o);     \
    ga.z += __shfl_xor_sync(0xffffffffu,ga.z,o);     \
    ga.w += __shfl_xor_sync(0xffffffffu,ga.w,o);     \
    gb.x += __shfl_xor_sync(0xffffffffu,gb.x,o);     \
    gb.y += __shfl_xor_sync(0xffffffffu,gb.y,o);     \
    gb.z += __shfl_xor_sync(0xffffffffu,gb.z,o);     \
    gb.w += __shfl_xor_sync(0xffffffffu,gb.w,o);     \
    gc.x += __shfl_xor_sync(0xffffffffu,gc.x,o);     \
    gc.y += __shfl_xor_sync(0xffffffffu,gc.y,o);     \
    gc.z += __shfl_xor_sync(0xffffffffu,gc.z,o);     \
  }while(0)

/* posted slot: [0..3]=a, [4..7]=b(.w=target0), [8..10]=targets1..3, [11]=sig */
static __device__ __forceinline__ void post_sig(int slot, int bid,
                                                float4 a, float4 b, float4 c,
                                                unsigned sig){
  float* mp = (float*)&g_part[(slot*NB + bid)*3];
  stcg4((float4*)mp,     a);
  stcg4((float4*)mp + 1, b);
  stcg1(mp+8,  c.x); stcg1(mp+9, c.y); stcg1(mp+10, c.z);
  st_rel((unsigned*)(mp+11), sig);
}

/* full bred + post (prologue/burn-in; ONE __syncthreads inside) */
static __device__ __forceinline__ void bred_post(int slot, int bid, unsigned sig,
                                                 float4 a, float4 b, float4 t,
                                                 float4* s_wA){
  #pragma unroll
  for (int o=16;o>0;o>>=1) SHFL8(0xffffffffu,o);
  int w = threadIdx.x >> 5;
  if ((threadIdx.x & 31) == 0 && threadIdx.x < NC){ s_wA[w]=a; s_wA[16+w]=b; }
  __syncthreads();
  if (threadIdx.x < 32){
    float4 z = make_float4(0.f,0.f,0.f,0.f);
    int l = threadIdx.x;
    a = (l<16) ? s_wA[l]    : z;
    b = (l<16) ? s_wA[16+l] : z;
    #pragma unroll
    for (int o=16;o>0;o>>=1) SHFL8(0xffffffffu,o);
    if (threadIdx.x == 0){
      b.w = t.x;
      post_sig(slot, bid, a, b, make_float4(t.y,t.z,t.w,0.f), sig);
    }
  }
}

static __device__ __forceinline__ float4 tred16(float4 t){
  #pragma unroll
  for (int o=8;o>0;o>>=1){
    t.x += __shfl_xor_sync(0x0000ffffu,t.x,o);
    t.y += __shfl_xor_sync(0x0000ffffu,t.y,o);
    t.z += __shfl_xor_sync(0x0000ffffu,t.z,o);
    t.w += __shfl_xor_sync(0x0000ffffu,t.w,o);
  }
  return t;
}

/* standalone gather (prologue/burn-in; TWO __syncthreads inside) */
static __device__ __forceinline__ void gather11(int slot, unsigned sigval,
                                                float4& A, float4& B, float4& C,
                                                float4* s_wB){
  __syncthreads();
  if (threadIdx.x < NB){
    const float* mp = (const float*)&g_part[(slot*NB + threadIdx.x)*3];
    while (ld_acq((const unsigned*)(mp+11)) < sigval) npause();
    float4 ga = ldcg4((const float4*)mp);
    float4 gb = ldcg4((const float4*)mp + 1);
    float4 gc = ldcg4((const float4*)mp + 2);
    #pragma unroll
    for (int o=16;o>0;o>>=1) SHFL11S(o);
    if ((threadIdx.x & 31) == 0){
      int w = threadIdx.x >> 5;
      s_wB[w]=ga; s_wB[4+w]=gb; s_wB[8+w]=gc;
    }
  }
  __syncthreads();
  float4 a = s_wB[0], b = s_wB[4], c = s_wB[8];
  #pragma unroll
  for (int i=1;i<4;i++){
    f4add(a, s_wB[i]); f4add(b, s_wB[4+i]);
    c.x += s_wB[8+i].x; c.y += s_wB[8+i].y; c.z += s_wB[8+i].z;
  }
  A=a; B=b; C=c;
}

__global__ void __launch_bounds__(NTH, 1)
ipls_kernel(const float* __restrict__ x,      const float* __restrict__ y,
            const float* __restrict__ mux,    const float* __restrict__ muy,
            const float* __restrict__ u_in,   const float* __restrict__ Wz_in,
            const float* __restrict__ Cz_in,  const float* __restrict__ tss_in,
            const float* __restrict__ bz_in,  const float* __restrict__ P_in,
            const int* __restrict__ n_in,     float* __restrict__ out)
{
  __shared__ float4 s_wA[32];
  __shared__ float4 s_wB[12];
  __shared__ float4 s_wT[1];

  const int tid = threadIdx.x, bid = blockIdx.x;
  const bool feat = (tid < NC);
  const bool yown = (tid < YSL4);
  const unsigned base = ld_acq(&g_sig[bid]);

  const int n   = n_in[0];
  const float fn1  = (float)(n + 1);
  const float fden = (float)(n + 2);

  const float4* W4 = (const float4*)Wz_in;
  const float4* P4 = (const float4*)P_in;
  const float4* C4 = (const float4*)Cz_in;
  const int fidx = bid*FB4 + tid;

  /* ---- init: feature slice + target slice + prefetch (compute only) ---- */
  float4 xr = make_float4(0.f,0.f,0.f,0.f);
  float4 yrs = xr, wcur = xr, wnext = xr, wnext2 = xr, pc = xr, pn1 = xr;
  float4 czs0 = xr, czs1 = xr, czs2 = xr;
  if (feat){
    float4 xv = ((const float4*)x)[fidx];
    float4 mv = ((const float4*)mux)[fidx];
    float4 mu;
    mu.x = (mv.x*fn1 + xv.x)/fden; mu.y = (mv.y*fn1 + xv.y)/fden;
    mu.z = (mv.z*fn1 + xv.z)/fden; mu.w = (mv.w*fn1 + xv.w)/fden;
    ((float4*)out)[fidx] = mu;
    xr.x = xv.x-mu.x; xr.y = xv.y-mu.y; xr.z = xv.z-mu.z; xr.w = xv.w-mu.w;

    wcur   = ldcg4(W4 + fidx);
    wnext  = ldcg4(W4 + (size_t)(NFEAT/4)   + fidx);
    wnext2 = ldcg4(W4 + (size_t)2*(NFEAT/4) + fidx);
    pc     = ldcg4(P4 + fidx);
    pn1    = ldcg4(P4 + (size_t)(NFEAT/4)   + fidx);
  }
  if (yown){
    int gi = bid*YSL4 + tid;
    float4 yv = ((const float4*)y)[gi];
    float4 mv = ((const float4*)muy)[gi];
    float4 mu;
    mu.x = (mv.x*fn1 + yv.x)/fden; mu.y = (mv.y*fn1 + yv.y)/fden;
    mu.z = (mv.z*fn1 + yv.z)/fden; mu.w = (mv.w*fn1 + yv.w)/fden;
    ((float4*)(out + OFF_MUY))[gi] = mu;
    yrs.x = yv.x-mu.x; yrs.y = yv.y-mu.y; yrs.z = yv.z-mu.z; yrs.w = yv.w-mu.w;
    czs0 = ldcg4(C4 + bid*YSL4 + tid);
    czs1 = ldcg4(C4 + YF4   + bid*YSL4 + tid);
    czs2 = ldcg4(C4 + 2*YF4 + bid*YSL4 + tid);
  }

  /* ---- burn-in path (n_new <= 3) ---- */
  if (n + 1 <= 3){
    for (int c=0;c<NLAT;c++){
      float4 a = make_float4(0.f,0.f,0.f,0.f);
      float4 b = a;
      if (feat){
        float u_c = u_in[c];
        float4 w = (c==0) ? wcur : ((c==1) ? wnext : ((c==2) ? wnext2
                 : ldcg4(W4 + (size_t)c*(NFEAT/4) + fidx)));
        float4 wz = f4fma(xr, u_c, w);
        stcg4(((float4*)(out + OFF_WZ)) + (size_t)c*(NFEAT/4) + fidx, wz);
        a = make_float4(d4(xr,wz), d4(wz,wz), 0.f, 0.f);
      }
      bred_post(c, bid, base + 1u + (unsigned)c, a, b, b, s_wA);
      __syncthreads();
    }

    if (bid == 0){
      for (int c=0;c<NLAT;c++){
        float4 ga, gb, gc;
        gather11(c, base + 1u + (unsigned)c, ga, gb, gc, s_wB);
        if (tid == 0){
          float tzb = ga.x / (sqrtf(ga.y) + EPSV);
          out[OFF_TSS + c] = tss_in[c] + tzb*tzb;
          out[OFF_U   + c] = u_in[c];
          out[OFF_BZ  + c] = bz_in[c];
        }
      }
    }
    if (feat){
      int g = bid*NC + tid;
      ((float4*)(out + OFF_CZ))[g] = ((const float4*)Cz_in)[g];
      #pragma unroll 4
      for (int k=0;k<(NLAT*NFEAT/4)/(NB*NC);k++)
        ((float4*)(out + OFF_P))[k*NB*NC + g] = P4[k*NB*NC + g];
    }
    __syncthreads();
    if (tid == 0) st_rel(&g_sig[bid], base + 1000u);
    return;
  }

  /* prologue post slot0: direct invariants of comp 0 */
  {
    float4 t = make_float4(0.f,0.f,0.f,0.f);
    if (yown)
      t = tred16(make_float4(d4(czs0,yrs), d4(czs0,czs0), d4(yrs,yrs), 0.f));
    float4 a = make_float4(0.f,0.f,0.f,0.f), b = a;
    if (feat) a = make_float4(d4(xr,wcur), d4(wcur,wcur), d4(xr,xr), 0.f);
    bred_post(0, bid, base + 1u, a, b, t, s_wA);
    __syncthreads();
  }
  /* prologue post slot1: raw-dot format for comp 1 (xr0 basis) */
  {
    float4 t = make_float4(0.f,0.f,0.f,0.f);
    if (yown)
      t = tred16(make_float4(d4(czs1,yrs), 0.f, d4(czs1,czs0), d4(czs1,czs1)));
    float4 a = make_float4(0.f,0.f,0.f,0.f), b = a;
    if (feat){
      a = make_float4(d4(xr,wnext), 0.f, d4(pc,wnext), d4(wnext,wnext));
      b = make_float4(d4(xr,pc), 0.f, d4(pc,pc), 0.f);
    }
    bred_post(1, bid, base + 2u, a, b, t, s_wA);
  }

  /* gather comp-0 invariants */
  float A, B, Q, E, F, G;
  {
    float4 ga, gb, gc;
    gather11(0, base + 1u, ga, gb, gc, s_wB);
    A = ga.x; B = ga.y; Q = ga.z; F = gb.w; E = gc.x; G = gc.y;
  }
  float t_p = 0.f, dd_p = 1.f, ss_p = 1.f, kk_p = 0.f;

  /* ---- main scan: comm-warp overlapped, 2 named barriers per iter ---- */
  for (int c=0;c<NLAT;c++){
    const bool do_post   = (c+2 < NLAT);
    const bool do_gather = (c+1 < NLAT);

    if (feat){
      const size_t frow = (size_t)c*(NFEAT/4) + fidx;

      if (do_post){
        if (yown){
          float4 tp = tred16(make_float4(d4(czs2,yrs),  d4(czs2,czs0),
                                         d4(czs2,czs1), d4(czs2,czs2)));
          if (tid == 0) s_wT[0] = tp;
        }
        float4 a = make_float4(d4(xr,wnext2), d4(pc,wnext2),
                               d4(pn1,wnext2), d4(wnext2,wnext2));
        float4 b = make_float4(d4(xr,pn1), d4(pc,pn1), d4(pn1,pn1), 0.f);
        #pragma unroll
        for (int o=16;o>0;o>>=1) SHFL8(0xffffffffu,o);
        int w = tid >> 5;
        if ((tid & 31) == 0){ s_wA[w]=a; s_wA[16+w]=b; }
      }
      BAR1();

      /* scalar chain comp c */
      const float u0   = u_in[c];
      const float tss0 = tss_in[c];
      const float bz0  = bz_in[c];

      float tz1  = (A + u0*Q) / (sqrtf(fmaxf(B + 2.f*u0*A + u0*u0*Q, 0.f)) + EPSV);
      float tss1 = tss0 + tz1*tz1;
      float t1   = tz1 / sqrtf(tss1);
      float c21  = fmaxf(E + 2.f*t1*F + t1*t1*G, 0.f);
      float u1   = (F + t1*G) / sqrtf(c21);

      float tz   = (A + u1*Q) / (sqrtf(fmaxf(B + 2.f*u1*A + u1*u1*Q, 0.f)) + EPSV);
      float tss_ = tss0 + tz*tz;
      float t    = tz / sqrtf(tss_);
      float c2   = fmaxf(E + 2.f*t*F + t*t*G, 0.f);
      float rc2  = rsqrtf(c2);
      float u_f  = (F + t*G) * rc2;
      float bz_new = bz0 + u_f*tz;
      float bb   = bz_new / sqrtf(tss_);
      float kk   = bb * t * rc2;
      float ss   = 1.f - kk*t;
      float dd   = 1.f - t*t;

      /* vector work */
      stcg4(((float4*)(out + OFF_WZ)) + frow, f4fma(xr, u1, wcur));
      if (yown){
        float4 czk = f4fma(yrs, t, czs0);
        stcg4(((float4*)(out + OFF_CZ)) + (size_t)c*YF4 + bid*YSL4 + tid, czk);
        yrs = f4fma(czk, -kk, yrs);
      }
      if (bid == 0 && tid == 0){
        out[OFF_U   + c] = u_f;
        out[OFF_TSS + c] = tss_;
        out[OFF_BZ  + c] = bz_new;
      }
      float4 pn = f4fma(xr, t, pc);
      stcg4(((float4*)(out + OFF_P)) + frow, pn);
      xr = f4fma(pn, -t, xr);

      float Gn = ss*ss*G - 2.f*ss*kk*F + kk*kk*E;

      /* shift + prefetch */
      wcur = wnext; wnext = wnext2;
      if (c+3 < NLAT)
        wnext2 = ldcg4(W4 + (size_t)(c+3)*(NFEAT/4) + fidx);
      pc = pn1;
      if (c+2 < NLAT)
        pn1 = ldcg4(P4 + (size_t)(c+2)*(NFEAT/4) + fidx);
      czs0 = czs1; czs1 = czs2;
      if (yown && c+3 < NLAT)
        czs2 = ldcg4(C4 + (size_t)(c+3)*YF4 + bid*YSL4 + tid);
      else
        czs2 = make_float4(0.f,0.f,0.f,0.f);

      BAR2();

      if (do_gather){
        float4 ga = s_wB[0], gb = s_wB[1], gc = s_wB[2];
        A = dd*fmaf(dd_p, ga.x, -t_p*ga.y) - t*ga.z;
        B = ga.w;
        float xrP = fmaf(dd_p, gb.x, -t_p*gb.y);
        Q = dd*dd*Q - 2.f*t*dd*xrP + t*t*gb.z;
        F = ss*fmaf(ss_p, gb.w, -kk_p*gc.x) - kk*gc.y;
        E = gc.z;
        G = Gn;
        t_p = t; dd_p = dd; ss_p = ss; kk_p = kk;
      }
    } else {
      /* ======== comm warp (tids 512-543) ======== */
      BAR1();
      if (do_post){
        float4 a, b;
        {
          float4 z = make_float4(0.f,0.f,0.f,0.f);
          int l = tid - NC;
          a = (l<16) ? s_wA[l]    : z;
          b = (l<16) ? s_wA[16+l] : z;
          #pragma unroll
          for (int o=16;o>0;o>>=1) SHFL8(0xffffffffu,o);
        }
        if (tid == NC){
          float4 tp = s_wT[0];
          b.w = tp.x;
          post_sig(c+2, bid, a, b, make_float4(tp.y,tp.z,tp.w,0.f),
                   base + 3u + (unsigned)c);
        }
      }
      if (do_gather){
        const int l = tid - NC;               /* 0..31, 4 slots each */
        const unsigned sigval = base + 2u + (unsigned)c;
        float4 ga = make_float4(0.f,0.f,0.f,0.f);
        float4 gb = ga, gc = ga;
        #pragma unroll
        for (int k=0;k<4;k++){
          const float* mp = (const float*)&g_part[((c+1)*NB + l*4 + k)*3];
          while (ld_acq((const unsigned*)(mp+11)) < sigval) npause();
          float4 pa = ldcg4((const float4*)mp);
          float4 pb = ldcg4((const float4*)mp + 1);
          float4 pcv= ldcg4((const float4*)mp + 2);
          f4add(ga, pa); f4add(gb, pb);
          gc.x += pcv.x; gc.y += pcv.y; gc.z += pcv.z;
        }
        #pragma unroll
        for (int o=16;o>0;o>>=1) SHFL11S(o);
        if (tid == NC){ s_wB[0]=ga; s_wB[1]=gb; s_wB[2]=gc; }
      }
      BAR2();
    }
  }

  __syncthreads();
  if (tid == 0) st_rel(&g_sig[bid], base + 1000u);
}

extern "C" void kernel_launch(void* const* d_in, const int* in_sizes, int n_in,
                              void* d_out, int out_size)
{
  (void)in_sizes; (void)n_in; (void)out_size;
  ipls_kernel<<<NB, NTH>>>(
      (const float*)d_in[0],  (const float*)d_in[1],
      (const float*)d_in[2],  (const float*)d_in[3],
      (const float*)d_in[4],  (const float*)d_in[5],
      (const float*)d_in[6],  (const float*)d_in[7],
      (const float*)d_in[8],  (const float*)d_in[9],
      (const int*)  d_in[10], (float*)d_out);
}